// round 7
// baseline (speedup 1.0000x reference)
#include <cuda_runtime.h>
#include <cstdint>

// yolo_detect_target: scores[N,80], boxes[N,4]
// score_i = max_c scores[i,c]; keep = cumprod(score >= 0.25)
// out = sum(keep * score) + sum(keep * rowsum(boxes))
//
// Single fused kernel, threadfence-reduction pattern WITHOUT the threadfence:
// each block publishes its (seg_sum, seg_fail) and then does a single
// atom.add.acq_rel.gpu on a done-counter. Release semantics order the seg
// writes before the increment; the last block's increment (acquire)
// synchronizes-with every prior release, and __syncthreads() publishes that
// ordering to the whole block. R3/R6 showed the membar.gl version costs
// ~12us (HBM 6.02 -> 5.48 TB/s); this is the cheap replacement under test.

#define NCH 80
#define ROWS_PER_BLOCK 256
#define MAX_SEGS 16384

__device__ float        g_seg_sum[MAX_SEGS];
__device__ int          g_seg_fail[MAX_SEGS];
__device__ unsigned int g_done_count = 0;

__global__ void __launch_bounds__(256) yolo_fused(
    const float* __restrict__ post,
    const float* __restrict__ boxes,
    float* __restrict__ out,
    int N)
{
    const float CONF = 0.25f;
    const int tid  = threadIdx.x;
    const int lane = tid & 31;
    const int warp = tid >> 5;
    const int nseg = gridDim.x;
    int row = blockIdx.x * ROWS_PER_BLOCK + tid;

    // ---- phase A: per-segment partial ----
    float mx = 0.0f;
    float bsum = 0.0f;
    if (row < N) {
        const float4* p = reinterpret_cast<const float4*>(post) + (size_t)row * (NCH / 4);
        #pragma unroll
        for (int i = 0; i < NCH / 4; ++i) {
            float4 v = p[i];
            mx = fmaxf(mx, fmaxf(fmaxf(v.x, v.y), fmaxf(v.z, v.w)));
        }
        float4 b = reinterpret_cast<const float4*>(boxes)[row];
        bsum = b.x + b.y + b.z + b.w;
    }

    bool fail = (row < N) && (mx < CONF);
    unsigned bal = __ballot_sync(0xffffffffu, fail);

    __shared__ int   s_fail[ROWS_PER_BLOCK / 32];
    __shared__ float s_sum [ROWS_PER_BLOCK / 32];
    __shared__ bool  s_last;

    if (lane == 0) {
        s_fail[warp] = bal ? (blockIdx.x * ROWS_PER_BLOCK + warp * 32 + (__ffs(bal) - 1))
                           : 0x7fffffff;
    }
    __syncthreads();

    int bf = 0x7fffffff;
    #pragma unroll
    for (int i = 0; i < ROWS_PER_BLOCK / 32; ++i) bf = min(bf, s_fail[i]);

    float val = (row < N && row < bf) ? (mx + bsum) : 0.0f;
    #pragma unroll
    for (int off = 16; off > 0; off >>= 1)
        val += __shfl_down_sync(0xffffffffu, val, off);
    if (lane == 0) s_sum[warp] = val;
    __syncthreads();

    if (tid == 0) {
        float acc = 0.0f;
        #pragma unroll
        for (int i = 0; i < ROWS_PER_BLOCK / 32; ++i) acc += s_sum[i];
        g_seg_sum[blockIdx.x]  = acc;
        g_seg_fail[blockIdx.x] = bf;
        // release-increment: orders the two STGs above before the counter
        // bump without a full membar.gl; acquire side sees all releases.
        unsigned old;
        asm volatile("atom.acq_rel.gpu.global.add.u32 %0, [%1], %2;"
                     : "=r"(old)
                     : "l"(&g_done_count), "r"(1u)
                     : "memory");
        s_last = (old == (unsigned)(nseg - 1));
    }
    __syncthreads();   // publishes tid0's acquire ordering block-wide

    if (!s_last) return;

    // ---- phase B: last block reduces all segments (L2-hot) ----
    __shared__ int   r_min[ROWS_PER_BLOCK / 32];
    __shared__ float r_sum[ROWS_PER_BLOCK / 32];

    int mn = 0x7fffffff;
    for (int s = tid; s < nseg; s += ROWS_PER_BLOCK) mn = min(mn, g_seg_fail[s]);
    #pragma unroll
    for (int off = 16; off > 0; off >>= 1)
        mn = min(mn, __shfl_down_sync(0xffffffffu, mn, off));
    if (lane == 0) r_min[warp] = mn;
    __syncthreads();
    if (tid == 0) {
        int m = 0x7fffffff;
        #pragma unroll
        for (int i = 0; i < ROWS_PER_BLOCK / 32; ++i) m = min(m, r_min[i]);
        r_min[0] = m;
    }
    __syncthreads();
    const int F = r_min[0];                 // global first failing row (or INT_MAX)
    const int failseg = F / ROWS_PER_BLOCK; // segments <= failseg contribute

    float acc = 0.0f;
    for (int s = tid; s < nseg; s += ROWS_PER_BLOCK)
        if (s <= failseg) acc += g_seg_sum[s];
    #pragma unroll
    for (int off = 16; off > 0; off >>= 1)
        acc += __shfl_down_sync(0xffffffffu, acc, off);
    if (lane == 0) r_sum[warp] = acc;
    __syncthreads();
    if (tid == 0) {
        float a = 0.0f;
        #pragma unroll
        for (int i = 0; i < ROWS_PER_BLOCK / 32; ++i) a += r_sum[i];
        out[0] = a;
        g_done_count = 0;                   // reset for next graph replay
    }
}

extern "C" void kernel_launch(void* const* d_in, const int* in_sizes, int n_in,
                              void* d_out, int out_size)
{
    const float* post  = (const float*)d_in[0];  // [N, 80]
    const float* boxes = (const float*)d_in[1];  // [N, 4]
    int N = in_sizes[0] / NCH;
    int nseg = (N + ROWS_PER_BLOCK - 1) / ROWS_PER_BLOCK;

    yolo_fused<<<nseg, ROWS_PER_BLOCK>>>(post, boxes, (float*)d_out, N);
}

// round 10
// speedup vs baseline: 1.0272x; 1.0272x over previous
#include <cuda_runtime.h>
#include <cstdint>

// yolo_detect_target: scores[N,80], boxes[N,4]
// score_i = max_c scores[i,c]; keep = cumprod(score >= 0.25)
// out = sum(keep * score) + sum(keep * rowsum(boxes))
//
// Fused, decoupled-retirement scheme:
//  - worker blocks: per 256-row segment -> (first local failing row or
//    INT_MAX, sum of (score+boxsum) for rows before it), publish, then
//    red.release.gpu.add (NO return value) and exit immediately. No CTA
//    waits on an atomic round-trip (R6/R7 showed the returning same-address
//    atomic + syncthreads smears ~10us across the tail waves).
//  - the last block spins on ld.acquire.gpu of the counter, then reduces all
//    segments (L2-hot): F = min fail, answer = sum seg_sum[s] for s<=F/256.
//    Resets the counter for graph replay.

#define NCH 80
#define ROWS_PER_BLOCK 256
#define MAX_SEGS 16384

__device__ float        g_seg_sum[MAX_SEGS];
__device__ int          g_seg_fail[MAX_SEGS];
__device__ unsigned int g_done_count = 0;

__global__ void __launch_bounds__(256) yolo_fused(
    const float* __restrict__ post,
    const float* __restrict__ boxes,
    float* __restrict__ out,
    int N)
{
    const float CONF = 0.25f;
    const int tid  = threadIdx.x;
    const int lane = tid & 31;
    const int warp = tid >> 5;
    const int nseg = gridDim.x;
    const bool is_spinner = (blockIdx.x == (unsigned)(nseg - 1));
    int row = blockIdx.x * ROWS_PER_BLOCK + tid;

    // ---- phase A: per-segment partial (all blocks, spinner included) ----
    float mx = 0.0f;
    float bsum = 0.0f;
    if (row < N) {
        const float4* p = reinterpret_cast<const float4*>(post) + (size_t)row * (NCH / 4);
        #pragma unroll
        for (int i = 0; i < NCH / 4; ++i) {
            float4 v = p[i];
            mx = fmaxf(mx, fmaxf(fmaxf(v.x, v.y), fmaxf(v.z, v.w)));
        }
        float4 b = reinterpret_cast<const float4*>(boxes)[row];
        bsum = b.x + b.y + b.z + b.w;
    }

    bool fail = (row < N) && (mx < CONF);
    unsigned bal = __ballot_sync(0xffffffffu, fail);

    __shared__ int   s_fail[ROWS_PER_BLOCK / 32];
    __shared__ float s_sum [ROWS_PER_BLOCK / 32];

    if (lane == 0) {
        s_fail[warp] = bal ? (blockIdx.x * ROWS_PER_BLOCK + warp * 32 + (__ffs(bal) - 1))
                           : 0x7fffffff;
    }
    __syncthreads();

    int bf = 0x7fffffff;
    #pragma unroll
    for (int i = 0; i < ROWS_PER_BLOCK / 32; ++i) bf = min(bf, s_fail[i]);

    float val = (row < N && row < bf) ? (mx + bsum) : 0.0f;
    #pragma unroll
    for (int off = 16; off > 0; off >>= 1)
        val += __shfl_down_sync(0xffffffffu, val, off);
    if (lane == 0) s_sum[warp] = val;
    __syncthreads();

    if (tid == 0) {
        float acc = 0.0f;
        #pragma unroll
        for (int i = 0; i < ROWS_PER_BLOCK / 32; ++i) acc += s_sum[i];
        g_seg_sum[blockIdx.x]  = acc;
        g_seg_fail[blockIdx.x] = bf;
        if (!is_spinner) {
            // fire-and-forget release increment; CTA retires immediately
            asm volatile("red.release.gpu.global.add.u32 [%0], %1;"
                         :: "l"(&g_done_count), "r"(1u) : "memory");
        }
    }

    if (!is_spinner) return;   // workers exit with no atomic round-trip wait

    // ---- spinner: wait for all nseg-1 workers, then reduce (L2-hot) ----
    if (tid == 0) {
        const unsigned target = (unsigned)(nseg - 1);
        unsigned v;
        do {
            asm volatile("ld.acquire.gpu.global.u32 %0, [%1];"
                         : "=r"(v) : "l"(&g_done_count));
            if (v >= target) break;
            __nanosleep(200);
        } while (true);
    }
    __syncthreads();   // publish tid0's acquire ordering block-wide

    __shared__ int   r_min[ROWS_PER_BLOCK / 32];
    __shared__ float r_sum[ROWS_PER_BLOCK / 32];

    int mn = 0x7fffffff;
    for (int s = tid; s < nseg; s += ROWS_PER_BLOCK) mn = min(mn, g_seg_fail[s]);
    #pragma unroll
    for (int off = 16; off > 0; off >>= 1)
        mn = min(mn, __shfl_down_sync(0xffffffffu, mn, off));
    if (lane == 0) r_min[warp] = mn;
    __syncthreads();
    if (tid == 0) {
        int m = 0x7fffffff;
        #pragma unroll
        for (int i = 0; i < ROWS_PER_BLOCK / 32; ++i) m = min(m, r_min[i]);
        r_min[0] = m;
    }
    __syncthreads();
    const int F = r_min[0];                 // global first failing row (or INT_MAX)
    const int failseg = F / ROWS_PER_BLOCK; // segments <= failseg contribute

    float acc = 0.0f;
    for (int s = tid; s < nseg; s += ROWS_PER_BLOCK)
        if (s <= failseg) acc += g_seg_sum[s];
    #pragma unroll
    for (int off = 16; off > 0; off >>= 1)
        acc += __shfl_down_sync(0xffffffffu, acc, off);
    if (lane == 0) r_sum[warp] = acc;
    __syncthreads();
    if (tid == 0) {
        float a = 0.0f;
        #pragma unroll
        for (int i = 0; i < ROWS_PER_BLOCK / 32; ++i) a += r_sum[i];
        out[0] = a;
        g_done_count = 0;                   // reset for next graph replay
    }
}

extern "C" void kernel_launch(void* const* d_in, const int* in_sizes, int n_in,
                              void* d_out, int out_size)
{
    const float* post  = (const float*)d_in[0];  // [N, 80]
    const float* boxes = (const float*)d_in[1];  // [N, 4]
    int N = in_sizes[0] / NCH;
    int nseg = (N + ROWS_PER_BLOCK - 1) / ROWS_PER_BLOCK;

    yolo_fused<<<nseg, ROWS_PER_BLOCK>>>(post, boxes, (float*)d_out, N);
}